// round 2
// baseline (speedup 1.0000x reference)
#include <cuda_runtime.h>

// ProbsToSpan: per batch b,
//   predicted_start[b] = argmax_s ( start[b,s] * suffix_max(end[b,:])[s] )
//   predicted_end[b]   = argmax_t ( end[b,t]   * prefix_max(start[b,:])[t] )
// Exactly equivalent to the reference's triu(outer)+max+argmax because the
// probabilities are nonnegative and fp32 multiply is monotone.
//
// S = 4096, B = 16. One CTA per batch, 512 threads, 8 elements per thread.

#define S_LEN 4096
#define NT    512
#define CHK   8   // elements per thread

__global__ __launch_bounds__(NT)
void probs_to_span_kernel(const float* __restrict__ start_p,
                          const float* __restrict__ end_p,
                          float* __restrict__ out, int B) {
    __shared__ float cmE[NT];   // chunk max of end   -> suffix scan
    __shared__ float cmS[NT];   // chunk max of start -> prefix scan
    __shared__ float rv[NT];
    __shared__ int   ri[NT];

    const int b = blockIdx.x;
    const int t = threadIdx.x;

    const float4* sp = (const float4*)(start_p + (size_t)b * S_LEN);
    const float4* ep = (const float4*)(end_p   + (size_t)b * S_LEN);

    // Each thread owns contiguous elements [t*8, t*8+8). Two float4 loads each
    // (MLP=4 per array) — one DRAM round trip total.
    float4 s0 = sp[2 * t], s1 = sp[2 * t + 1];
    float4 e0 = ep[2 * t], e1 = ep[2 * t + 1];

    float s[CHK] = {s0.x, s0.y, s0.z, s0.w, s1.x, s1.y, s1.z, s1.w};
    float e[CHK] = {e0.x, e0.y, e0.z, e0.w, e1.x, e1.y, e1.z, e1.w};

    float emax = e[0], smax = s[0];
#pragma unroll
    for (int j = 1; j < CHK; j++) {
        emax = fmaxf(emax, e[j]);
        smax = fmaxf(smax, s[j]);
    }
    cmE[t] = emax;
    cmS[t] = smax;
    __syncthreads();

    // Hillis-Steele max-scan: cmE reverse-inclusive (suffix), cmS forward-inclusive (prefix).
#pragma unroll
    for (int off = 1; off < NT; off <<= 1) {
        float vE = (t + off < NT) ? cmE[t + off] : -1e30f;
        float vS = (t >= off)     ? cmS[t - off] : -1e30f;
        __syncthreads();
        cmE[t] = fmaxf(cmE[t], vE);
        cmS[t] = fmaxf(cmS[t], vS);
        __syncthreads();
    }

    // Suffix max of end beyond this thread's chunk; prefix max of start before it.
    const float tailE = (t + 1 < NT) ? cmE[t + 1] : -1e30f;
    const float headS = (t > 0)      ? cmS[t - 1] : -1e30f;

    // --- best start: f[i] = start[i] * suffmax_end[i] ---
    float suff[CHK];
    float runE = tailE;
#pragma unroll
    for (int j = CHK - 1; j >= 0; j--) {
        runE = fmaxf(runE, e[j]);
        suff[j] = runE;
    }
    float bsv = -1e30f; int bsi = 0;
#pragma unroll
    for (int j = 0; j < CHK; j++) {
        float f = s[j] * suff[j];
        if (f > bsv) { bsv = f; bsi = t * CHK + j; }   // strict > => first occurrence
    }

    // --- best end: g[i] = end[i] * prefmax_start[i] ---
    float runS = headS;
    float bev = -1e30f; int bei = 0;
#pragma unroll
    for (int j = 0; j < CHK; j++) {
        runS = fmaxf(runS, s[j]);
        float g = e[j] * runS;
        if (g > bev) { bev = g; bei = t * CHK + j; }
    }

    // --- argmax reduction (tie -> smaller index), for start then end ---
    rv[t] = bsv; ri[t] = bsi;
    __syncthreads();
#pragma unroll
    for (int sft = NT / 2; sft > 0; sft >>= 1) {
        if (t < sft) {
            float ov = rv[t + sft]; int oi = ri[t + sft];
            if (ov > rv[t] || (ov == rv[t] && oi < ri[t])) { rv[t] = ov; ri[t] = oi; }
        }
        __syncthreads();
    }
    if (t == 0) out[b] = (float)ri[0];
    __syncthreads();

    rv[t] = bev; ri[t] = bei;
    __syncthreads();
#pragma unroll
    for (int sft = NT / 2; sft > 0; sft >>= 1) {
        if (t < sft) {
            float ov = rv[t + sft]; int oi = ri[t + sft];
            if (ov > rv[t] || (ov == rv[t] && oi < ri[t])) { rv[t] = ov; ri[t] = oi; }
        }
        __syncthreads();
    }
    if (t == 0) out[B + b] = (float)ri[0];
}

extern "C" void kernel_launch(void* const* d_in, const int* in_sizes, int n_in,
                              void* d_out, int out_size) {
    const float* start_p = (const float*)d_in[0];
    const float* end_p   = (const float*)d_in[1];
    float* out = (float*)d_out;

    const int B = in_sizes[0] / S_LEN;  // 16
    probs_to_span_kernel<<<B, NT>>>(start_p, end_p, out, B);
}

// round 6
// speedup vs baseline: 1.2651x; 1.2651x over previous
#include <cuda_runtime.h>

// ProbsToSpan: per batch b,
//   predicted_start[b] = argmax_s ( start[b,s] * suffix_max(end[b,:])[s] )
//   predicted_end[b]   = argmax_t ( end[b,t]   * prefix_max(start[b,:])[t] )
// Exact vs. reference (nonneg probs => monotone fp32 multiply; tie -> first idx).
//
// S=4096, B=16. One CTA/batch, 512 threads (16 warps), 8 elems/thread.
// Warp-shuffle scans + packed-u64 argmax: only 2 __syncthreads total.

#define S_LEN 4096
#define NT    512
#define NW    16    // warps
#define CHK   8     // elements per thread

#define NEGBIG (-1e30f)

__device__ __forceinline__ unsigned long long pack_key(float v, int idx) {
    // v >= 0 always => float bits are order-monotone as uint.
    // ~idx in low word => equal value resolves to SMALLER index under max.
    return ((unsigned long long)__float_as_uint(v) << 32) |
           (unsigned long long)(0xFFFFFFFFu - (unsigned)idx);
}

__global__ __launch_bounds__(NT)
void probs_to_span_kernel(const float* __restrict__ start_p,
                          const float* __restrict__ end_p,
                          float* __restrict__ out, int B) {
    __shared__ float wS[NW];                     // per-warp total max(start)
    __shared__ float wE[NW];                     // per-warp total max(end)
    __shared__ unsigned long long aS[NW], aE[NW];

    const int b    = blockIdx.x;
    const int t    = threadIdx.x;
    const int w    = t >> 5;
    const int lane = t & 31;

    const float4* sp = (const float4*)(start_p + (size_t)b * S_LEN);
    const float4* ep = (const float4*)(end_p   + (size_t)b * S_LEN);

    float4 s0 = sp[2 * t], s1 = sp[2 * t + 1];
    float4 e0 = ep[2 * t], e1 = ep[2 * t + 1];

    float s[CHK] = {s0.x, s0.y, s0.z, s0.w, s1.x, s1.y, s1.z, s1.w};
    float e[CHK] = {e0.x, e0.y, e0.z, e0.w, e1.x, e1.y, e1.z, e1.w};

    float smax = s[0], emax = e[0];
#pragma unroll
    for (int j = 1; j < CHK; j++) {
        smax = fmaxf(smax, s[j]);
        emax = fmaxf(emax, e[j]);
    }

    // Warp-level inclusive prefix max of smax (by lane) and suffix max of emax.
    float ps = smax, se = emax;
#pragma unroll
    for (int off = 1; off < 32; off <<= 1) {
        float vU = __shfl_up_sync(0xFFFFFFFFu, ps, off);
        float vD = __shfl_down_sync(0xFFFFFFFFu, se, off);
        if (lane >= off)      ps = fmaxf(ps, vU);
        if (lane + off < 32)  se = fmaxf(se, vD);
    }

    // Publish warp totals.
    if (lane == 31) wS[w] = ps;   // inclusive prefix at lane31 == warp total
    if (lane == 0)  wE[w] = se;   // inclusive suffix at lane0  == warp total
    __syncthreads();

    // Cross-warp exclusive head(start) / tail(end) for this warp (broadcast LDS).
    float headS = NEGBIG, tailE = NEGBIG;
#pragma unroll
    for (int i = 0; i < NW; i++) {
        if (i < w) headS = fmaxf(headS, wS[i]);
        if (i > w) tailE = fmaxf(tailE, wE[i]);
    }

    // Exclusive within-warp versions.
    float exS = __shfl_up_sync(0xFFFFFFFFu, ps, 1);
    float exE = __shfl_down_sync(0xFFFFFFFFu, se, 1);
    if (lane == 0)  exS = NEGBIG;
    if (lane == 31) exE = NEGBIG;

    const float preS = fmaxf(headS, exS);   // max(start) strictly before this chunk
    const float sufE = fmaxf(tailE, exE);   // max(end)   strictly after  this chunk

    // Per-element candidates, packed.
    float suff[CHK];
    float runE = sufE;
#pragma unroll
    for (int j = CHK - 1; j >= 0; j--) {
        runE = fmaxf(runE, e[j]);
        suff[j] = runE;
    }
    unsigned long long kS = 0ull, kE = 0ull;
    float runS = preS;
#pragma unroll
    for (int j = 0; j < CHK; j++) {
        int idx = t * CHK + j;
        unsigned long long cs = pack_key(s[j] * suff[j], idx);
        if (cs > kS) kS = cs;
        runS = fmaxf(runS, s[j]);
        unsigned long long ce = pack_key(e[j] * runS, idx);
        if (ce > kE) kE = ce;
    }

    // Warp argmax reduce (both keys in the same shuffle ladder).
#pragma unroll
    for (int off = 16; off > 0; off >>= 1) {
        unsigned long long oS = __shfl_xor_sync(0xFFFFFFFFu, kS, off);
        unsigned long long oE = __shfl_xor_sync(0xFFFFFFFFu, kE, off);
        if (oS > kS) kS = oS;
        if (oE > kE) kE = oE;
    }
    if (lane == 0) { aS[w] = kS; aE[w] = kE; }
    __syncthreads();

    // Warp 0 finishes start, warp 1 finishes end (16-entry reduce via shuffles).
    if (w < 2) {
        unsigned long long k = 0ull;
        if (lane < NW) k = (w == 0) ? aS[lane] : aE[lane];
#pragma unroll
        for (int off = 8; off > 0; off >>= 1) {
            unsigned long long o = __shfl_xor_sync(0xFFFFFFFFu, k, off);
            if (o > k) k = o;
        }
        if (lane == 0) {
            int idx = (int)(0xFFFFFFFFu - (unsigned)(k & 0xFFFFFFFFull));
            out[(w == 0 ? 0 : B) + b] = (float)idx;
        }
    }
}

extern "C" void kernel_launch(void* const* d_in, const int* in_sizes, int n_in,
                              void* d_out, int out_size) {
    const float* start_p = (const float*)d_in[0];
    const float* end_p   = (const float*)d_in[1];
    float* out = (float*)d_out;

    const int B = in_sizes[0] / S_LEN;  // 16
    probs_to_span_kernel<<<B, NT>>>(start_p, end_p, out, B);
}

// round 7
// speedup vs baseline: 1.3077x; 1.0337x over previous
#include <cuda_runtime.h>

// ProbsToSpan: per batch b,
//   predicted_start[b] = argmax_s ( start[b,s] * suffix_max(end[b,:])[s] )
//   predicted_end[b]   = argmax_t ( end[b,t]   * prefix_max(start[b,:])[t] )
// Exact vs. reference (nonneg probs => monotone fp32 multiply; tie -> first idx).
//
// S=4096, B=16. One CTA/batch, 512 threads (16 warps), 8 elems/thread.
// Warp-shuffle scans; argmax via hardware REDUX (__reduce_max_sync) +
// ballot + single shfl. Only 2 __syncthreads total.

#define S_LEN 4096
#define NT    512
#define NW    16    // warps
#define CHK   8     // elements per thread

#define NEGBIG (-1e30f)
#define FULLM  0xFFFFFFFFu

__global__ __launch_bounds__(NT)
void probs_to_span_kernel(const float* __restrict__ start_p,
                          const float* __restrict__ end_p,
                          float* __restrict__ out, int B) {
    __shared__ float wS[NW];            // per-warp total max(start)
    __shared__ float wE[NW];            // per-warp total max(end)
    __shared__ unsigned aVS[NW], aVE[NW];  // per-warp best value bits
    __shared__ int      aIS[NW], aIE[NW];  // per-warp best index

    const int b    = blockIdx.x;
    const int t    = threadIdx.x;
    const int w    = t >> 5;
    const int lane = t & 31;

    const float4* sp = (const float4*)(start_p + (size_t)b * S_LEN);
    const float4* ep = (const float4*)(end_p   + (size_t)b * S_LEN);

    float4 s0 = sp[2 * t], s1 = sp[2 * t + 1];
    float4 e0 = ep[2 * t], e1 = ep[2 * t + 1];

    float s[CHK] = {s0.x, s0.y, s0.z, s0.w, s1.x, s1.y, s1.z, s1.w};
    float e[CHK] = {e0.x, e0.y, e0.z, e0.w, e1.x, e1.y, e1.z, e1.w};

    float smax = s[0], emax = e[0];
#pragma unroll
    for (int j = 1; j < CHK; j++) {
        smax = fmaxf(smax, s[j]);
        emax = fmaxf(emax, e[j]);
    }

    // Warp-level inclusive prefix max of smax (by lane) and suffix max of emax.
    float ps = smax, se = emax;
#pragma unroll
    for (int off = 1; off < 32; off <<= 1) {
        float vU = __shfl_up_sync(FULLM, ps, off);
        float vD = __shfl_down_sync(FULLM, se, off);
        if (lane >= off)      ps = fmaxf(ps, vU);
        if (lane + off < 32)  se = fmaxf(se, vD);
    }

    // Publish warp totals.
    if (lane == 31) wS[w] = ps;   // inclusive prefix at lane31 == warp total
    if (lane == 0)  wE[w] = se;   // inclusive suffix at lane0  == warp total
    __syncthreads();

    // Cross-warp exclusive head(start) / tail(end) for this warp (broadcast LDS).
    float headS = NEGBIG, tailE = NEGBIG;
#pragma unroll
    for (int i = 0; i < NW; i++) {
        if (i < w) headS = fmaxf(headS, wS[i]);
        if (i > w) tailE = fmaxf(tailE, wE[i]);
    }

    // Exclusive within-warp versions.
    float exS = __shfl_up_sync(FULLM, ps, 1);
    float exE = __shfl_down_sync(FULLM, se, 1);
    if (lane == 0)  exS = NEGBIG;
    if (lane == 31) exE = NEGBIG;

    const float preS = fmaxf(headS, exS);   // max(start) strictly before this chunk
    const float sufE = fmaxf(tailE, exE);   // max(end)   strictly after  this chunk

    // Per-element candidates; per-thread best keeps FIRST (smallest-index) max.
    float suff[CHK];
    float runE = sufE;
#pragma unroll
    for (int j = CHK - 1; j >= 0; j--) {
        runE = fmaxf(runE, e[j]);
        suff[j] = runE;
    }
    float bvS = -1.0f, bvE = -1.0f;   // all candidates >= 0, so -1 < any
    int   biS = 0,     biE = 0;
    float runS = preS;
#pragma unroll
    for (int j = 0; j < CHK; j++) {
        int idx = t * CHK + j;
        float f = s[j] * suff[j];
        if (f > bvS) { bvS = f; biS = idx; }   // strict > => first occurrence
        runS = fmaxf(runS, s[j]);
        float g = e[j] * runS;
        if (g > bvE) { bvE = g; biE = idx; }
    }

    // Warp argmax via REDUX on fp32 bits (nonneg => order-monotone), then
    // ballot: lowest matching lane holds the smallest index (lane order == index order).
    {
        unsigned vb = __float_as_uint(fmaxf(bvS, 0.0f));
        unsigned m  = __reduce_max_sync(FULLM, vb);
        unsigned msk = __ballot_sync(FULLM, vb == m);
        int src = __ffs(msk) - 1;
        int idx = __shfl_sync(FULLM, biS, src);
        if (lane == 0) { aVS[w] = m; aIS[w] = idx; }
    }
    {
        unsigned vb = __float_as_uint(fmaxf(bvE, 0.0f));
        unsigned m  = __reduce_max_sync(FULLM, vb);
        unsigned msk = __ballot_sync(FULLM, vb == m);
        int src = __ffs(msk) - 1;
        int idx = __shfl_sync(FULLM, biE, src);
        if (lane == 0) { aVE[w] = m; aIE[w] = idx; }
    }
    __syncthreads();

    // Warp 0 finishes start, warp 1 finishes end. Lane order == warp order ==
    // index-block order, so lowest matching lane again gives smallest index.
    if (w < 2) {
        unsigned vb = 0u;
        int idx = 0;
        if (lane < NW) {
            vb  = (w == 0) ? aVS[lane] : aVE[lane];
            idx = (w == 0) ? aIS[lane] : aIE[lane];
        }
        unsigned m   = __reduce_max_sync(FULLM, vb);
        unsigned msk = __ballot_sync(FULLM, vb == m && lane < NW);
        int src = __ffs(msk) - 1;
        int ans = __shfl_sync(FULLM, idx, src);
        if (lane == 0) out[(w == 0 ? 0 : B) + b] = (float)ans;
    }
}

extern "C" void kernel_launch(void* const* d_in, const int* in_sizes, int n_in,
                              void* d_out, int out_size) {
    const float* start_p = (const float*)d_in[0];
    const float* end_p   = (const float*)d_in[1];
    float* out = (float*)d_out;

    const int B = in_sizes[0] / S_LEN;  // 16
    probs_to_span_kernel<<<B, NT>>>(start_p, end_p, out, B);
}